// round 14
// baseline (speedup 1.0000x reference)
#include <cuda_runtime.h>
#include <cuda_fp16.h>
#include <cstdint>

// TitansMemoryModule — R13: fused last-CTA epilogue, DEPTH=6, GEMM1 deferred stores.
//   retrieved = k @ W^T ; G1 = k^T k (upper blocks, symmetric) ; G2 = v^T k
// 512 thr: w0-7 producers, w8-11 GEMM1 (M=32), w12-15 reductions; last CTA runs epilogue.

#define D     64
#define TILE  128
#define PH    72
#define DEPTH 6

static constexpr int KBUF  = TILE * PH;
static constexpr int STAGE = 2 * KBUF;
static constexpr int SMEM_HALVES = DEPTH * STAGE + D * PH;
static constexpr int SMEM_BYTES  = SMEM_HALVES * 2;   // 230400 B (< 232448 cap)

__device__ float g_G1[D * D];     // zero-init at load; re-zeroed by epilogue
__device__ float g_G2[D * D];
__device__ float g_ksum[D];
__device__ float g_sv;
__device__ int   g_done;

__device__ __forceinline__ uint32_t sh_u32(const void* p) {
    return (uint32_t)__cvta_generic_to_shared(p);
}
__device__ __forceinline__ void ldsm4(uint32_t& r0, uint32_t& r1, uint32_t& r2, uint32_t& r3, uint32_t a) {
    asm volatile("ldmatrix.sync.aligned.m8n8.x4.shared.b16 {%0,%1,%2,%3},[%4];"
                 : "=r"(r0), "=r"(r1), "=r"(r2), "=r"(r3) : "r"(a));
}
__device__ __forceinline__ void ldsm4t(uint32_t& r0, uint32_t& r1, uint32_t& r2, uint32_t& r3, uint32_t a) {
    asm volatile("ldmatrix.sync.aligned.m8n8.x4.trans.shared.b16 {%0,%1,%2,%3},[%4];"
                 : "=r"(r0), "=r"(r1), "=r"(r2), "=r"(r3) : "r"(a));
}
__device__ __forceinline__ void mma16(float* c,
                                      uint32_t a0, uint32_t a1, uint32_t a2, uint32_t a3,
                                      uint32_t b0, uint32_t b1) {
    asm volatile("mma.sync.aligned.m16n8k16.row.col.f32.f16.f16.f32 "
                 "{%0,%1,%2,%3},{%4,%5,%6,%7},{%8,%9},{%0,%1,%2,%3};"
                 : "+f"(c[0]), "+f"(c[1]), "+f"(c[2]), "+f"(c[3])
                 : "r"(a0), "r"(a1), "r"(a2), "r"(a3), "r"(b0), "r"(b1));
}
__device__ __forceinline__ void mbar_init(uint32_t a, uint32_t cnt) {
    asm volatile("mbarrier.init.shared.b64 [%0], %1;" :: "r"(a), "r"(cnt) : "memory");
}
__device__ __forceinline__ void mbar_arrive(uint32_t a) {
    asm volatile("mbarrier.arrive.shared.b64 _, [%0];" :: "r"(a) : "memory");
}
__device__ __forceinline__ void mbar_wait(uint32_t a, uint32_t parity) {
    asm volatile(
        "{\n\t.reg .pred P;\n"
        "WL_%=:\n\t"
        "mbarrier.try_wait.parity.acquire.cta.shared::cta.b64 P, [%0], %1, 0x989680;\n\t"
        "@P bra WD_%=;\n\t"
        "bra WL_%=;\n"
        "WD_%=:\n\t}"
        :: "r"(a), "r"(parity) : "memory");
}

// ---- reduction fragment helpers ----
__device__ __forceinline__ void ldAfrag(uint32_t* f, const __half* mb, int sb, int ar, int lane) {
    const int asel = ((lane >> 4) << 3) + (lane & 7);
    const int aoff = ((lane >> 3) & 1) * 8;
    ldsm4t(f[0], f[1], f[2], f[3], sh_u32(&mb[(sb + asel) * PH + ar * 16 + aoff]));
}
__device__ __forceinline__ void ldBfrag(uint32_t* f, const __half* kb, int sb, int ac, int lane) {
    const int bsel = ((lane >> 3) & 1) * 8 + (lane & 7);
    const int boff = (lane >> 4) * 8;
    ldsm4t(f[0], f[1], f[2], f[3], sh_u32(&kb[(sb + bsel) * PH + ac * 16 + boff]));
}
__device__ __forceinline__ void bmma(float* acc, const uint32_t* A, const uint32_t* B) {
    mma16(acc,     A[0], A[1], A[2], A[3], B[0], B[1]);
    mma16(acc + 4, A[0], A[1], A[2], A[3], B[2], B[3]);
}

// writeout tables: enc = src<<4 | ar<<2 | ac
static __device__ const int RW_TBL[4][7] = {
    { 0,  1,  2,  3,  5,  6,  7},
    {10, 11, 15, 16, 17, 18, 19},
    {20, 21, 22, 23, 24, 25, 25},
    {26, 27, 28, 29, 30, 31, 31},
};
static __device__ const int RW_CNT[4] = {7, 7, 6, 6};

// Per-tile reduction routines; arrive-empty issued inside last kk after its loads.
__device__ __forceinline__ void red_tile_w0(float (&acc)[7][8], const __half* kb, const __half*,
                                            int lane, uint32_t ebar) {
#pragma unroll
    for (int kk = 0; kk < 8; kk++) {
        const int sb = kk * 16;
        uint32_t A0[4], A1[4], B[4][4];
        ldAfrag(A0, kb, sb, 0, lane); ldAfrag(A1, kb, sb, 1, lane);
#pragma unroll
        for (int ac = 0; ac < 4; ac++) ldBfrag(B[ac], kb, sb, ac, lane);
        if (kk == 7 && lane == 0) mbar_arrive(ebar);
        bmma(acc[0], A0, B[0]); bmma(acc[1], A0, B[1]);
        bmma(acc[2], A0, B[2]); bmma(acc[3], A0, B[3]);
        bmma(acc[4], A1, B[1]); bmma(acc[5], A1, B[2]); bmma(acc[6], A1, B[3]);
    }
}
__device__ __forceinline__ void red_tile_w1(float (&acc)[7][8], const __half* kb, const __half* vb,
                                            int lane, uint32_t ebar) {
#pragma unroll
    for (int kk = 0; kk < 8; kk++) {
        const int sb = kk * 16;
        uint32_t A2[4], A3[4], AV[4], B[4][4];
        ldAfrag(A2, kb, sb, 2, lane); ldAfrag(A3, kb, sb, 3, lane); ldAfrag(AV, vb, sb, 0, lane);
#pragma unroll
        for (int ac = 0; ac < 4; ac++) ldBfrag(B[ac], kb, sb, ac, lane);
        if (kk == 7 && lane == 0) mbar_arrive(ebar);
        bmma(acc[0], A2, B[2]); bmma(acc[1], A2, B[3]); bmma(acc[2], A3, B[3]);
        bmma(acc[3], AV, B[0]); bmma(acc[4], AV, B[1]);
        bmma(acc[5], AV, B[2]); bmma(acc[6], AV, B[3]);
    }
}
__device__ __forceinline__ void red_tile_w2(float (&acc)[7][8], const __half* kb, const __half* vb,
                                            int lane, uint32_t ebar) {
#pragma unroll
    for (int kk = 0; kk < 8; kk++) {
        const int sb = kk * 16;
        uint32_t A1[4], A2[4], B[4][4];
        ldAfrag(A1, vb, sb, 1, lane); ldAfrag(A2, vb, sb, 2, lane);
#pragma unroll
        for (int ac = 0; ac < 4; ac++) ldBfrag(B[ac], kb, sb, ac, lane);
        if (kk == 7 && lane == 0) mbar_arrive(ebar);
        bmma(acc[0], A1, B[0]); bmma(acc[1], A1, B[1]);
        bmma(acc[2], A1, B[2]); bmma(acc[3], A1, B[3]);
        bmma(acc[4], A2, B[0]); bmma(acc[5], A2, B[1]);
    }
}
__device__ __forceinline__ void red_tile_w3(float (&acc)[7][8], const __half* kb, const __half* vb,
                                            int lane, uint32_t ebar) {
#pragma unroll
    for (int kk = 0; kk < 8; kk++) {
        const int sb = kk * 16;
        uint32_t A2[4], A3[4], B[4][4];
        ldAfrag(A2, vb, sb, 2, lane); ldAfrag(A3, vb, sb, 3, lane);
#pragma unroll
        for (int ac = 0; ac < 4; ac++) ldBfrag(B[ac], kb, sb, ac, lane);
        if (kk == 7 && lane == 0) mbar_arrive(ebar);
        bmma(acc[0], A2, B[2]); bmma(acc[1], A2, B[3]);
        bmma(acc[2], A3, B[0]); bmma(acc[3], A3, B[1]);
        bmma(acc[4], A3, B[2]); bmma(acc[5], A3, B[3]);
    }
}

__global__ __launch_bounds__(512, 1)
void titans_main_kernel(const float* __restrict__ kmat,
                        const float* __restrict__ vmat,
                        const float* __restrict__ W,
                        const float* __restrict__ gate_w,
                        const float* __restrict__ gate_b,
                        const float* __restrict__ S,
                        float* __restrict__ ret,
                        int N) {
    extern __shared__ __half sh[];
    __shared__ uint64_t mbar[2 * DEPTH];
    __shared__ float gates_sh[3];
    __shared__ float sc_sh;
    __shared__ int   is_last;
    __half* wsh = sh + DEPTH * STAGE;

    const int tid  = threadIdx.x;
    const int lane = tid & 31;
    const int warp = tid >> 5;

    if (tid == 0) {
#pragma unroll
        for (int s = 0; s < DEPTH; s++) {
            mbar_init(sh_u32(&mbar[s]), 8);            // full: 8 producer warps
            mbar_init(sh_u32(&mbar[DEPTH + s]), 8);    // empty: 8 consumer warps
        }
    }
    for (int i = tid; i < D * D; i += 512)
        wsh[(i >> 6) * PH + (i & 63)] = __float2half(W[i]);
    __syncthreads();

    const int grid   = gridDim.x;
    const int ntiles = N / TILE;

    if (warp < 8) {
        // ======== PRODUCERS: w0-3 k, w4-7 v (cross-tile register prefetch) ========
        const bool isK  = warp < 4;
        const int  pt   = isK ? tid : (tid - 128);
        const int  qcol = (pt & 15) * 4;
        const float4* src = reinterpret_cast<const float4*>(isK ? kmat : vmat);
        const int  boff = isK ? 0 : KBUF;

        float acc4[4] = {0.f, 0.f, 0.f, 0.f};

        float4 c0[8], c1r[8];
        {
            const float4* t0 = src + (size_t)blockIdx.x * 2048;
#pragma unroll
            for (int j = 0; j < 8; j++) c0[j]  = __ldcs(&t0[pt + j * 128]);
#pragma unroll
            for (int j = 0; j < 8; j++) c1r[j] = __ldcs(&t0[pt + (j + 8) * 128]);
        }

        int stage = 0, phase = 1;
        for (int tile = blockIdx.x; tile < ntiles; tile += grid) {
            int nt = tile + grid; if (nt >= ntiles) nt = tile;
            const float4* tn = src + (size_t)nt * 2048;

            mbar_wait(sh_u32(&mbar[DEPTH + stage]), phase);
            __half* dst = sh + stage * STAGE + boff;

#pragma unroll
            for (int j = 0; j < 8; j++) {
                float4 x = c0[j];
                int r = (pt + j * 128) >> 4;
                if (isK) { acc4[0] += x.x; acc4[1] += x.y; acc4[2] += x.z; acc4[3] += x.w; }
                else     { acc4[0] += x.x * x.x + x.y * x.y + x.z * x.z + x.w * x.w; }
                __half2 h01 = __floats2half2_rn(x.x, x.y);
                __half2 h23 = __floats2half2_rn(x.z, x.w);
                *reinterpret_cast<uint2*>(&dst[r * PH + qcol]) =
                    make_uint2(*reinterpret_cast<uint32_t*>(&h01), *reinterpret_cast<uint32_t*>(&h23));
            }
#pragma unroll
            for (int j = 0; j < 8; j++) c0[j] = __ldcs(&tn[pt + j * 128]);

#pragma unroll
            for (int j = 0; j < 8; j++) {
                float4 x = c1r[j];
                int r = (pt + (j + 8) * 128) >> 4;
                if (isK) { acc4[0] += x.x; acc4[1] += x.y; acc4[2] += x.z; acc4[3] += x.w; }
                else     { acc4[0] += x.x * x.x + x.y * x.y + x.z * x.z + x.w * x.w; }
                __half2 h01 = __floats2half2_rn(x.x, x.y);
                __half2 h23 = __floats2half2_rn(x.z, x.w);
                *reinterpret_cast<uint2*>(&dst[r * PH + qcol]) =
                    make_uint2(*reinterpret_cast<uint32_t*>(&h01), *reinterpret_cast<uint32_t*>(&h23));
            }
#pragma unroll
            for (int j = 0; j < 8; j++) c1r[j] = __ldcs(&tn[pt + (j + 8) * 128]);

            __syncwarp();
            if (lane == 0) mbar_arrive(sh_u32(&mbar[stage]));
            stage++; if (stage == DEPTH) { stage = 0; phase ^= 1; }
        }

        if (isK) {
#pragma unroll
            for (int c = 0; c < 4; c++) atomicAdd(&g_ksum[qcol + c], acc4[c]);
        } else {
            float sv = acc4[0];
#pragma unroll
            for (int off = 16; off > 0; off >>= 1) sv += __shfl_xor_sync(0xFFFFFFFF, sv, off);
            if (lane == 0) atomicAdd(&g_sv, sv);
        }

    } else if (warp < 12) {
        // ======== GEMM1 warps (4): M=32, deferred stripe-0 stores ========
        const int widx = warp - 8;
        const int lp = lane >> 2, lq = lane & 3;

        uint32_t wr[4][4][4];
#pragma unroll
        for (int kk = 0; kk < 4; kk++)
#pragma unroll
            for (int j = 0; j < 4; j++) {
                const int bt = (2 * j + (lane >> 4)) * 8 + (lane & 7);
                const int bc = kk * 16 + ((lane >> 3) & 1) * 8;
                ldsm4(wr[kk][j][0], wr[kk][j][1], wr[kk][j][2], wr[kk][j][3],
                      sh_u32(&wsh[bt * PH + bc]));
            }

        const int rbase0 = widx * 32;
        const int rbase1 = widx * 32 + 16;

        int stage = 0, phase = 0;
        for (int tile = blockIdx.x; tile < ntiles; tile += grid) {
            mbar_wait(sh_u32(&mbar[stage]), phase);
            const __half* kb = sh + stage * STAGE;

            uint32_t af[4][4];
            float c1[8][4];

            // stripe 0: ldsm + mma (stores deferred)
#pragma unroll
            for (int kk = 0; kk < 4; kk++)
                ldsm4(af[kk][0], af[kk][1], af[kk][2], af[kk][3],
                      sh_u32(&kb[(rbase0 + (lane & 15)) * PH + kk * 16 + ((lane >> 4) << 3)]));
#pragma unroll
            for (int n = 0; n < 8; n++)
#pragma unroll
                for (int i = 0; i < 4; i++) c1[n][i] = 0.0f;
#pragma unroll
            for (int kk = 0; kk < 4; kk++)
#pragma unroll
                for (int j = 0; j < 4; j++) {
                    mma16(c1[2 * j],     af[kk][0], af[kk][1], af[kk][2], af[kk][3],
                          wr[kk][j][0], wr[kk][j][1]);
                    mma16(c1[2 * j + 1], af[kk][0], af[kk][1], af[kk][2], af[kk][3],
                          wr[kk][j][2], wr[kk][j][3]);
                }

            // stripe 1: ldsm (af reuse), then release stage
#pragma unroll
            for (int kk = 0; kk < 4; kk++)
                ldsm4(af[kk][0], af[kk][1], af[kk][2], af[kk][3],
                      sh_u32(&kb[(rbase1 + (lane & 15)) * PH + kk * 16 + ((lane >> 4) << 3)]));
            if (lane == 0) mbar_arrive(sh_u32(&mbar[DEPTH + stage]));

            // stripe 0 stores
            const size_t gr0 = (size_t)(tile * TILE + rbase0 + lp) * D;
#pragma unroll
            for (int n = 0; n < 8; n++) {
                const int col = n * 8 + 2 * lq;
                __stcs(reinterpret_cast<float2*>(&ret[gr0 + col]),
                       make_float2(c1[n][0], c1[n][1]));
                __stcs(reinterpret_cast<float2*>(&ret[gr0 + 8 * D + col]),
                       make_float2(c1[n][2], c1[n][3]));
            }

            // stripe 1 mma + stores
#pragma unroll
            for (int n = 0; n < 8; n++)
#pragma unroll
                for (int i = 0; i < 4; i++) c1[n][i] = 0.0f;
#pragma unroll
            for (int kk = 0; kk < 4; kk++)
#pragma unroll
                for (int j = 0; j < 4; j++) {
                    mma16(c1[2 * j],     af[kk][0], af[kk][1], af[kk][2], af[kk][3],
                          wr[kk][j][0], wr[kk][j][1]);
                    mma16(c1[2 * j + 1], af[kk][0], af[kk][1], af[kk][2], af[kk][3],
                          wr[kk][j][2], wr[kk][j][3]);
                }
            const size_t gr1 = (size_t)(tile * TILE + rbase1 + lp) * D;
#pragma unroll
            for (int n = 0; n < 8; n++) {
                const int col = n * 8 + 2 * lq;
                __stcs(reinterpret_cast<float2*>(&ret[gr1 + col]),
                       make_float2(c1[n][0], c1[n][1]));
                __stcs(reinterpret_cast<float2*>(&ret[gr1 + 8 * D + col]),
                       make_float2(c1[n][2], c1[n][3]));
            }
            stage++; if (stage == DEPTH) { stage = 0; phase ^= 1; }
        }

    } else {
        // ======== Reduction warps (4): symmetric G1 + G2, early empty-arrive ========
        const int ridx = warp - 12;
        const int lp = lane >> 2, lq = lane & 3;

        float acc[7][8];
#pragma unroll
        for (int b = 0; b < 7; b++)
#pragma unroll
            for (int i = 0; i < 8; i++) acc[b][i] = 0.0f;

        int stage = 0, phase = 0;
        for (int tile = blockIdx.x; tile < ntiles; tile += grid) {
            mbar_wait(sh_u32(&mbar[stage]), phase);
            const __half* kb = sh + stage * STAGE;
            const __half* vb = kb + KBUF;
            const uint32_t ebar = sh_u32(&mbar[DEPTH + stage]);

            if      (ridx == 0) red_tile_w0(acc, kb, vb, lane, ebar);
            else if (ridx == 1) red_tile_w1(acc, kb, vb, lane, ebar);
            else if (ridx == 2) red_tile_w2(acc, kb, vb, lane, ebar);
            else                red_tile_w3(acc, kb, vb, lane, ebar);

            stage++; if (stage == DEPTH) { stage = 0; phase ^= 1; }
        }

        const int cnt = RW_CNT[ridx];
        for (int b = 0; b < cnt; b++) {
            const int enc = RW_TBL[ridx][b];
            const int src = (enc >> 4) & 1, ar = (enc >> 2) & 3, ac = enc & 3;
            float* gd = src ? g_G2 : g_G1;
            const int r0 = (ar * 16 + lp) * D + ac * 16;
            const int r1 = (ar * 16 + 8 + lp) * D + ac * 16;
            atomicAdd(&gd[r0 + 2 * lq],         acc[b][0]);
            atomicAdd(&gd[r0 + 2 * lq + 1],     acc[b][1]);
            atomicAdd(&gd[r1 + 2 * lq],         acc[b][2]);
            atomicAdd(&gd[r1 + 2 * lq + 1],     acc[b][3]);
            atomicAdd(&gd[r0 + 8 + 2 * lq],     acc[b][4]);
            atomicAdd(&gd[r0 + 8 + 2 * lq + 1], acc[b][5]);
            atomicAdd(&gd[r1 + 8 + 2 * lq],     acc[b][6]);
            atomicAdd(&gd[r1 + 8 + 2 * lq + 1], acc[b][7]);
        }
    }

    // ================= fused epilogue: last CTA to finish does it =================
    __threadfence();
    __syncthreads();
    if (tid == 0) {
        int old = atomicAdd(&g_done, 1);
        is_last = (old == (int)gridDim.x - 1);
    }
    __syncthreads();
    if (!is_last) return;

    // reuse dynamic smem as float scratch
    float* fsh  = reinterpret_cast<float*>(sh);
    float* Wf   = fsh;            // 4096
    float* G1m  = fsh + 4096;     // 4096 (mirrored symmetric)
    float* G2f  = fsh + 8192;     // 4096
    float* red  = fsh + 12288;    // 512
    float* red2 = fsh + 12800;    // 512
    const float numel = (float)N * (float)D;

    const size_t loss_off = (size_t)N * D;
    const size_t nw_off   = loss_off + 1;
    const size_t ns_off   = nw_off + D * D;
    const size_t g_off    = ns_off + D * D;
    float* out = ret;   // out buffer == ret base

    // gates (warps 0-2)
    if (warp < 3) {
        const float invN = 1.0f / (float)N;
        float s = gate_w[warp * D + lane]      * (__ldcg(&g_ksum[lane])      * invN)
                + gate_w[warp * D + 32 + lane] * (__ldcg(&g_ksum[32 + lane]) * invN);
#pragma unroll
        for (int off = 16; off > 0; off >>= 1)
            s += __shfl_xor_sync(0xFFFFFFFF, s, off);
        if (lane == 0)
            gates_sh[warp] = 1.0f / (1.0f + __expf(-(s + gate_b[warp])));
    }
    for (int i = tid; i < D * D; i += 512) {
        Wf[i]  = W[i];
        G2f[i] = __ldcg(&g_G2[i]);
        const int j = i >> 6, d = i & 63;
        G1m[i] = ((j >> 4) <= (d >> 4)) ? __ldcg(&g_G1[i]) : __ldcg(&g_G1[(d << 6) | j]);
    }
    __syncthreads();

    const float alpha = gates_sh[0];
    const float eta   = gates_sh[1];
    const float theta = gates_sh[2];

    float nwv[8];
    float ssp = 0.0f, dlp = 0.0f;
#pragma unroll
    for (int e = 0; e < 8; e++) {
        const int idx = e * 512 + tid;
        const int j = idx >> 6, dp = idx & 63;
        float a = 0.0f;
#pragma unroll 8
        for (int d = 0; d < D; d++)
            a += Wf[j * D + d] * G1m[d * D + dp];
        const float w  = Wf[idx];
        const float g2 = G2f[idx];
        float g = (a - g2) * (2.0f / numel);
        g = fminf(1.0f, fmaxf(-1.0f, g));
        const float ns = eta * S[idx] - 0.01f * theta * g;
        const float nw = (1.0f - alpha) * w + ns;
        out[ns_off + idx] = ns;
        nwv[e] = nw;
        ssp += nw * nw;
        dlp += (a - 2.0f * g2) * w;
    }
    red[tid]  = ssp;
    red2[tid] = dlp;
    __syncthreads();
#pragma unroll
    for (int s = 256; s > 0; s >>= 1) {
        if (tid < s) { red[tid] += red[tid + s]; red2[tid] += red2[tid + s]; }
        __syncthreads();
    }
    if (tid == 0) {
        float wnorm = sqrtf(red[0]);
        sc_sh = (wnorm > 10.0f) ? (10.0f / (wnorm + 1e-8f)) : 1.0f;
        out[loss_off] = (__ldcg(&g_sv) + red2[0]) / numel;
    }
    __syncthreads();
    const float sc = sc_sh;
#pragma unroll
    for (int e = 0; e < 8; e++)
        out[nw_off + e * 512 + tid] = nwv[e] * sc;
    if (tid < 3) out[g_off + tid] = gates_sh[tid];

    // re-zero scratch for next graph replay
    __syncthreads();
    for (int i = tid; i < D * D; i += 512) { g_G1[i] = 0.0f; g_G2[i] = 0.0f; }
    if (tid < D) g_ksum[tid] = 0.0f;
    if (tid == 0) { g_sv = 0.0f; g_done = 0; }
}

extern "C" void kernel_launch(void* const* d_in, const int* in_sizes, int n_in,
                              void* d_out, int out_size) {
    const float* k  = (const float*)d_in[0];
    const float* v  = (const float*)d_in[1];
    const float* W  = (const float*)d_in[2];
    const float* gw = (const float*)d_in[3];
    const float* gb = (const float*)d_in[4];
    const float* S  = (const float*)d_in[5];
    float* out = (float*)d_out;

    const int N = in_sizes[0] / D;

    cudaFuncSetAttribute(titans_main_kernel,
                         cudaFuncAttributeMaxDynamicSharedMemorySize, SMEM_BYTES);

    titans_main_kernel<<<148, 512, SMEM_BYTES>>>(k, v, W, gw, gb, S, out, N);
}

// round 16
// speedup vs baseline: 1.1460x; 1.1460x over previous
#include <cuda_runtime.h>
#include <cuda_fp16.h>
#include <cstdint>

// TitansMemoryModule — R15: R12 config (DEPTH=5, 193KB smem) + fused last-CTA epilogue.
//   retrieved = k @ W^T ; G1 = k^T k (upper blocks, symmetric) ; G2 = v^T k
// 512 thr: w0-7 producers, w8-11 GEMM1 (M=32), w12-15 reductions; last CTA runs epilogue.

#define D     64
#define TILE  128
#define PH    72
#define DEPTH 5

static constexpr int KBUF  = TILE * PH;
static constexpr int STAGE = 2 * KBUF;
static constexpr int SMEM_HALVES = DEPTH * STAGE + D * PH;
static constexpr int SMEM_BYTES  = SMEM_HALVES * 2;   // 193536 B (leaves ~35KB L1)

__device__ float g_G1[D * D];     // zero-init at load; re-zeroed by epilogue
__device__ float g_G2[D * D];
__device__ float g_ksum[D];
__device__ float g_sv;
__device__ int   g_done;

__device__ __forceinline__ uint32_t sh_u32(const void* p) {
    return (uint32_t)__cvta_generic_to_shared(p);
}
__device__ __forceinline__ void ldsm4(uint32_t& r0, uint32_t& r1, uint32_t& r2, uint32_t& r3, uint32_t a) {
    asm volatile("ldmatrix.sync.aligned.m8n8.x4.shared.b16 {%0,%1,%2,%3},[%4];"
                 : "=r"(r0), "=r"(r1), "=r"(r2), "=r"(r3) : "r"(a));
}
__device__ __forceinline__ void ldsm4t(uint32_t& r0, uint32_t& r1, uint32_t& r2, uint32_t& r3, uint32_t a) {
    asm volatile("ldmatrix.sync.aligned.m8n8.x4.trans.shared.b16 {%0,%1,%2,%3},[%4];"
                 : "=r"(r0), "=r"(r1), "=r"(r2), "=r"(r3) : "r"(a));
}
__device__ __forceinline__ void mma16(float* c,
                                      uint32_t a0, uint32_t a1, uint32_t a2, uint32_t a3,
                                      uint32_t b0, uint32_t b1) {
    asm volatile("mma.sync.aligned.m16n8k16.row.col.f32.f16.f16.f32 "
                 "{%0,%1,%2,%3},{%4,%5,%6,%7},{%8,%9},{%0,%1,%2,%3};"
                 : "+f"(c[0]), "+f"(c[1]), "+f"(c[2]), "+f"(c[3])
                 : "r"(a0), "r"(a1), "r"(a2), "r"(a3), "r"(b0), "r"(b1));
}
__device__ __forceinline__ void mbar_init(uint32_t a, uint32_t cnt) {
    asm volatile("mbarrier.init.shared.b64 [%0], %1;" :: "r"(a), "r"(cnt) : "memory");
}
__device__ __forceinline__ void mbar_arrive(uint32_t a) {
    asm volatile("mbarrier.arrive.shared.b64 _, [%0];" :: "r"(a) : "memory");
}
__device__ __forceinline__ void mbar_wait(uint32_t a, uint32_t parity) {
    asm volatile(
        "{\n\t.reg .pred P;\n"
        "WL_%=:\n\t"
        "mbarrier.try_wait.parity.acquire.cta.shared::cta.b64 P, [%0], %1, 0x989680;\n\t"
        "@P bra WD_%=;\n\t"
        "bra WL_%=;\n"
        "WD_%=:\n\t}"
        :: "r"(a), "r"(parity) : "memory");
}

// ---- reduction fragment helpers ----
__device__ __forceinline__ void ldAfrag(uint32_t* f, const __half* mb, int sb, int ar, int lane) {
    const int asel = ((lane >> 4) << 3) + (lane & 7);
    const int aoff = ((lane >> 3) & 1) * 8;
    ldsm4t(f[0], f[1], f[2], f[3], sh_u32(&mb[(sb + asel) * PH + ar * 16 + aoff]));
}
__device__ __forceinline__ void ldBfrag(uint32_t* f, const __half* kb, int sb, int ac, int lane) {
    const int bsel = ((lane >> 3) & 1) * 8 + (lane & 7);
    const int boff = (lane >> 4) * 8;
    ldsm4t(f[0], f[1], f[2], f[3], sh_u32(&kb[(sb + bsel) * PH + ac * 16 + boff]));
}
__device__ __forceinline__ void bmma(float* acc, const uint32_t* A, const uint32_t* B) {
    mma16(acc,     A[0], A[1], A[2], A[3], B[0], B[1]);
    mma16(acc + 4, A[0], A[1], A[2], A[3], B[2], B[3]);
}

// writeout tables: enc = src<<4 | ar<<2 | ac
static __device__ const int RW_TBL[4][7] = {
    { 0,  1,  2,  3,  5,  6,  7},
    {10, 11, 15, 16, 17, 18, 19},
    {20, 21, 22, 23, 24, 25, 25},
    {26, 27, 28, 29, 30, 31, 31},
};
static __device__ const int RW_CNT[4] = {7, 7, 6, 6};

// Per-tile reduction routines; arrive-empty issued inside last kk after its loads.
__device__ __forceinline__ void red_tile_w0(float (&acc)[7][8], const __half* kb, const __half*,
                                            int lane, uint32_t ebar) {
#pragma unroll
    for (int kk = 0; kk < 8; kk++) {
        const int sb = kk * 16;
        uint32_t A0[4], A1[4], B[4][4];
        ldAfrag(A0, kb, sb, 0, lane); ldAfrag(A1, kb, sb, 1, lane);
#pragma unroll
        for (int ac = 0; ac < 4; ac++) ldBfrag(B[ac], kb, sb, ac, lane);
        if (kk == 7 && lane == 0) mbar_arrive(ebar);
        bmma(acc[0], A0, B[0]); bmma(acc[1], A0, B[1]);
        bmma(acc[2], A0, B[2]); bmma(acc[3], A0, B[3]);
        bmma(acc[4], A1, B[1]); bmma(acc[5], A1, B[2]); bmma(acc[6], A1, B[3]);
    }
}
__device__ __forceinline__ void red_tile_w1(float (&acc)[7][8], const __half* kb, const __half* vb,
                                            int lane, uint32_t ebar) {
#pragma unroll
    for (int kk = 0; kk < 8; kk++) {
        const int sb = kk * 16;
        uint32_t A2[4], A3[4], AV[4], B[4][4];
        ldAfrag(A2, kb, sb, 2, lane); ldAfrag(A3, kb, sb, 3, lane); ldAfrag(AV, vb, sb, 0, lane);
#pragma unroll
        for (int ac = 0; ac < 4; ac++) ldBfrag(B[ac], kb, sb, ac, lane);
        if (kk == 7 && lane == 0) mbar_arrive(ebar);
        bmma(acc[0], A2, B[2]); bmma(acc[1], A2, B[3]); bmma(acc[2], A3, B[3]);
        bmma(acc[3], AV, B[0]); bmma(acc[4], AV, B[1]);
        bmma(acc[5], AV, B[2]); bmma(acc[6], AV, B[3]);
    }
}
__device__ __forceinline__ void red_tile_w2(float (&acc)[7][8], const __half* kb, const __half* vb,
                                            int lane, uint32_t ebar) {
#pragma unroll
    for (int kk = 0; kk < 8; kk++) {
        const int sb = kk * 16;
        uint32_t A1[4], A2[4], B[4][4];
        ldAfrag(A1, vb, sb, 1, lane); ldAfrag(A2, vb, sb, 2, lane);
#pragma unroll
        for (int ac = 0; ac < 4; ac++) ldBfrag(B[ac], kb, sb, ac, lane);
        if (kk == 7 && lane == 0) mbar_arrive(ebar);
        bmma(acc[0], A1, B[0]); bmma(acc[1], A1, B[1]);
        bmma(acc[2], A1, B[2]); bmma(acc[3], A1, B[3]);
        bmma(acc[4], A2, B[0]); bmma(acc[5], A2, B[1]);
    }
}
__device__ __forceinline__ void red_tile_w3(float (&acc)[7][8], const __half* kb, const __half* vb,
                                            int lane, uint32_t ebar) {
#pragma unroll
    for (int kk = 0; kk < 8; kk++) {
        const int sb = kk * 16;
        uint32_t A2[4], A3[4], B[4][4];
        ldAfrag(A2, vb, sb, 2, lane); ldAfrag(A3, vb, sb, 3, lane);
#pragma unroll
        for (int ac = 0; ac < 4; ac++) ldBfrag(B[ac], kb, sb, ac, lane);
        if (kk == 7 && lane == 0) mbar_arrive(ebar);
        bmma(acc[0], A2, B[2]); bmma(acc[1], A2, B[3]);
        bmma(acc[2], A3, B[0]); bmma(acc[3], A3, B[1]);
        bmma(acc[4], A3, B[2]); bmma(acc[5], A3, B[3]);
    }
}

__global__ __launch_bounds__(512, 1)
void titans_main_kernel(const float* __restrict__ kmat,
                        const float* __restrict__ vmat,
                        const float* __restrict__ W,
                        const float* __restrict__ gate_w,
                        const float* __restrict__ gate_b,
                        const float* __restrict__ S,
                        float* __restrict__ ret,
                        int N) {
    extern __shared__ __half sh[];
    __shared__ uint64_t mbar[2 * DEPTH];
    __shared__ float gates_sh[3];
    __shared__ float sc_sh;
    __shared__ int   is_last;
    __half* wsh = sh + DEPTH * STAGE;

    const int tid  = threadIdx.x;
    const int lane = tid & 31;
    const int warp = tid >> 5;

    if (tid == 0) {
#pragma unroll
        for (int s = 0; s < DEPTH; s++) {
            mbar_init(sh_u32(&mbar[s]), 8);            // full: 8 producer warps
            mbar_init(sh_u32(&mbar[DEPTH + s]), 8);    // empty: 8 consumer warps
        }
    }
    for (int i = tid; i < D * D; i += 512)
        wsh[(i >> 6) * PH + (i & 63)] = __float2half(W[i]);
    __syncthreads();

    const int grid   = gridDim.x;
    const int ntiles = N / TILE;

    if (warp < 8) {
        // ======== PRODUCERS: w0-3 k, w4-7 v (cross-tile register prefetch) ========
        const bool isK  = warp < 4;
        const int  pt   = isK ? tid : (tid - 128);
        const int  qcol = (pt & 15) * 4;
        const float4* src = reinterpret_cast<const float4*>(isK ? kmat : vmat);
        const int  boff = isK ? 0 : KBUF;

        float acc4[4] = {0.f, 0.f, 0.f, 0.f};

        float4 c0[8], c1r[8];
        {
            const float4* t0 = src + (size_t)blockIdx.x * 2048;
#pragma unroll
            for (int j = 0; j < 8; j++) c0[j]  = __ldcs(&t0[pt + j * 128]);
#pragma unroll
            for (int j = 0; j < 8; j++) c1r[j] = __ldcs(&t0[pt + (j + 8) * 128]);
        }

        int stage = 0, phase = 1;
        for (int tile = blockIdx.x; tile < ntiles; tile += grid) {
            int nt = tile + grid; if (nt >= ntiles) nt = tile;
            const float4* tn = src + (size_t)nt * 2048;

            mbar_wait(sh_u32(&mbar[DEPTH + stage]), phase);
            __half* dst = sh + stage * STAGE + boff;

#pragma unroll
            for (int j = 0; j < 8; j++) {
                float4 x = c0[j];
                int r = (pt + j * 128) >> 4;
                if (isK) { acc4[0] += x.x; acc4[1] += x.y; acc4[2] += x.z; acc4[3] += x.w; }
                else     { acc4[0] += x.x * x.x + x.y * x.y + x.z * x.z + x.w * x.w; }
                __half2 h01 = __floats2half2_rn(x.x, x.y);
                __half2 h23 = __floats2half2_rn(x.z, x.w);
                *reinterpret_cast<uint2*>(&dst[r * PH + qcol]) =
                    make_uint2(*reinterpret_cast<uint32_t*>(&h01), *reinterpret_cast<uint32_t*>(&h23));
            }
#pragma unroll
            for (int j = 0; j < 8; j++) c0[j] = __ldcs(&tn[pt + j * 128]);

#pragma unroll
            for (int j = 0; j < 8; j++) {
                float4 x = c1r[j];
                int r = (pt + (j + 8) * 128) >> 4;
                if (isK) { acc4[0] += x.x; acc4[1] += x.y; acc4[2] += x.z; acc4[3] += x.w; }
                else     { acc4[0] += x.x * x.x + x.y * x.y + x.z * x.z + x.w * x.w; }
                __half2 h01 = __floats2half2_rn(x.x, x.y);
                __half2 h23 = __floats2half2_rn(x.z, x.w);
                *reinterpret_cast<uint2*>(&dst[r * PH + qcol]) =
                    make_uint2(*reinterpret_cast<uint32_t*>(&h01), *reinterpret_cast<uint32_t*>(&h23));
            }
#pragma unroll
            for (int j = 0; j < 8; j++) c1r[j] = __ldcs(&tn[pt + (j + 8) * 128]);

            __syncwarp();
            if (lane == 0) mbar_arrive(sh_u32(&mbar[stage]));
            stage++; if (stage == DEPTH) { stage = 0; phase ^= 1; }
        }

        if (isK) {
#pragma unroll
            for (int c = 0; c < 4; c++) atomicAdd(&g_ksum[qcol + c], acc4[c]);
        } else {
            float sv = acc4[0];
#pragma unroll
            for (int off = 16; off > 0; off >>= 1) sv += __shfl_xor_sync(0xFFFFFFFF, sv, off);
            if (lane == 0) atomicAdd(&g_sv, sv);
        }

    } else if (warp < 12) {
        // ======== GEMM1 warps (4): each M=32 (two 16-row stripes), R12 ordering ========
        const int widx = warp - 8;
        const int lp = lane >> 2, lq = lane & 3;

        uint32_t wr[4][4][4];
#pragma unroll
        for (int kk = 0; kk < 4; kk++)
#pragma unroll
            for (int j = 0; j < 4; j++) {
                const int bt = (2 * j + (lane >> 4)) * 8 + (lane & 7);
                const int bc = kk * 16 + ((lane >> 3) & 1) * 8;
                ldsm4(wr[kk][j][0], wr[kk][j][1], wr[kk][j][2], wr[kk][j][3],
                      sh_u32(&wsh[bt * PH + bc]));
            }

        int stage = 0, phase = 0;
        for (int tile = blockIdx.x; tile < ntiles; tile += grid) {
            mbar_wait(sh_u32(&mbar[stage]), phase);
            const __half* kb = sh + stage * STAGE;

#pragma unroll
            for (int s2 = 0; s2 < 2; s2++) {
                const int rbase = widx * 32 + s2 * 16;
                uint32_t af[4][4];
#pragma unroll
                for (int kk = 0; kk < 4; kk++)
                    ldsm4(af[kk][0], af[kk][1], af[kk][2], af[kk][3],
                          sh_u32(&kb[(rbase + (lane & 15)) * PH + kk * 16 + ((lane >> 4) << 3)]));
                if (s2 == 1 && lane == 0) mbar_arrive(sh_u32(&mbar[DEPTH + stage]));

                float c1[8][4];
#pragma unroll
                for (int n = 0; n < 8; n++)
#pragma unroll
                    for (int i = 0; i < 4; i++) c1[n][i] = 0.0f;
#pragma unroll
                for (int kk = 0; kk < 4; kk++)
#pragma unroll
                    for (int j = 0; j < 4; j++) {
                        mma16(c1[2 * j],     af[kk][0], af[kk][1], af[kk][2], af[kk][3],
                              wr[kk][j][0], wr[kk][j][1]);
                        mma16(c1[2 * j + 1], af[kk][0], af[kk][1], af[kk][2], af[kk][3],
                              wr[kk][j][2], wr[kk][j][3]);
                    }

                const size_t gr0 = (size_t)(tile * TILE + rbase + lp) * D;
#pragma unroll
                for (int n = 0; n < 8; n++) {
                    const int col = n * 8 + 2 * lq;
                    __stcs(reinterpret_cast<float2*>(&ret[gr0 + col]),
                           make_float2(c1[n][0], c1[n][1]));
                    __stcs(reinterpret_cast<float2*>(&ret[gr0 + 8 * D + col]),
                           make_float2(c1[n][2], c1[n][3]));
                }
            }
            stage++; if (stage == DEPTH) { stage = 0; phase ^= 1; }
        }

    } else {
        // ======== Reduction warps (4): symmetric G1 + G2, early empty-arrive ========
        const int ridx = warp - 12;
        const int lp = lane >> 2, lq = lane & 3;

        float acc[7][8];
#pragma unroll
        for (int b = 0; b < 7; b++)
#pragma unroll
            for (int i = 0; i < 8; i++) acc[b][i] = 0.0f;

        int stage = 0, phase = 0;
        for (int tile = blockIdx.x; tile < ntiles; tile += grid) {
            mbar_wait(sh_u32(&mbar[stage]), phase);
            const __half* kb = sh + stage * STAGE;
            const __half* vb = kb + KBUF;
            const uint32_t ebar = sh_u32(&mbar[DEPTH + stage]);

            if      (ridx == 0) red_tile_w0(acc, kb, vb, lane, ebar);
            else if (ridx == 1) red_tile_w1(acc, kb, vb, lane, ebar);
            else if (ridx == 2) red_tile_w2(acc, kb, vb, lane, ebar);
            else                red_tile_w3(acc, kb, vb, lane, ebar);

            stage++; if (stage == DEPTH) { stage = 0; phase ^= 1; }
        }

        const int cnt = RW_CNT[ridx];
        for (int b = 0; b < cnt; b++) {
            const int enc = RW_TBL[ridx][b];
            const int src = (enc >> 4) & 1, ar = (enc >> 2) & 3, ac = enc & 3;
            float* gd = src ? g_G2 : g_G1;
            const int r0 = (ar * 16 + lp) * D + ac * 16;
            const int r1 = (ar * 16 + 8 + lp) * D + ac * 16;
            atomicAdd(&gd[r0 + 2 * lq],         acc[b][0]);
            atomicAdd(&gd[r0 + 2 * lq + 1],     acc[b][1]);
            atomicAdd(&gd[r1 + 2 * lq],         acc[b][2]);
            atomicAdd(&gd[r1 + 2 * lq + 1],     acc[b][3]);
            atomicAdd(&gd[r0 + 8 + 2 * lq],     acc[b][4]);
            atomicAdd(&gd[r0 + 8 + 2 * lq + 1], acc[b][5]);
            atomicAdd(&gd[r1 + 8 + 2 * lq],     acc[b][6]);
            atomicAdd(&gd[r1 + 8 + 2 * lq + 1], acc[b][7]);
        }
    }

    // ================= fused epilogue: last CTA to finish does it =================
    __threadfence();
    __syncthreads();
    if (tid == 0) {
        int old = atomicAdd(&g_done, 1);
        is_last = (old == (int)gridDim.x - 1);
    }
    __syncthreads();
    if (!is_last) return;

    float* fsh  = reinterpret_cast<float*>(sh);
    float* Wf   = fsh;            // 4096
    float* G1m  = fsh + 4096;     // 4096 (mirrored symmetric)
    float* G2f  = fsh + 8192;     // 4096
    float* red  = fsh + 12288;    // 512
    float* red2 = fsh + 12800;    // 512
    const float numel = (float)N * (float)D;

    const size_t loss_off = (size_t)N * D;
    const size_t nw_off   = loss_off + 1;
    const size_t ns_off   = nw_off + D * D;
    const size_t g_off    = ns_off + D * D;
    float* out = ret;

    if (warp < 3) {
        const float invN = 1.0f / (float)N;
        float s = gate_w[warp * D + lane]      * (__ldcg(&g_ksum[lane])      * invN)
                + gate_w[warp * D + 32 + lane] * (__ldcg(&g_ksum[32 + lane]) * invN);
#pragma unroll
        for (int off = 16; off > 0; off >>= 1)
            s += __shfl_xor_sync(0xFFFFFFFF, s, off);
        if (lane == 0)
            gates_sh[warp] = 1.0f / (1.0f + __expf(-(s + gate_b[warp])));
    }
    for (int i = tid; i < D * D; i += 512) {
        Wf[i]  = W[i];
        G2f[i] = __ldcg(&g_G2[i]);
        const int j = i >> 6, d = i & 63;
        G1m[i] = ((j >> 4) <= (d >> 4)) ? __ldcg(&g_G1[i]) : __ldcg(&g_G1[(d << 6) | j]);
    }
    __syncthreads();

    const float alpha = gates_sh[0];
    const float eta   = gates_sh[1];
    const float theta = gates_sh[2];

    float nwv[8];
    float ssp = 0.0f, dlp = 0.0f;
#pragma unroll
    for (int e = 0; e < 8; e++) {
        const int idx = e * 512 + tid;
        const int j = idx >> 6, dp = idx & 63;
        float a = 0.0f;
#pragma unroll 8
        for (int d = 0; d < D; d++)
            a += Wf[j * D + d] * G1m[d * D + dp];
        const float w  = Wf[idx];
        const float g2 = G2f[idx];
        float g = (a - g2) * (2.0f / numel);
        g = fminf(1.0f, fmaxf(-1.0f, g));
        const float ns = eta * S[idx] - 0.01f * theta * g;
        const float nw = (1.0f - alpha) * w + ns;
        out[ns_off + idx] = ns;
        nwv[e] = nw;
        ssp += nw * nw;
        dlp += (a - 2.0f * g2) * w;
    }
    red[tid]  = ssp;
    red2[tid] = dlp;
    __syncthreads();
#pragma unroll
    for (int s = 256; s > 0; s >>= 1) {
        if (tid < s) { red[tid] += red[tid + s]; red2[tid] += red2[tid + s]; }
        __syncthreads();
    }
    if (tid == 0) {
        float wnorm = sqrtf(red[0]);
        sc_sh = (wnorm > 10.0f) ? (10.0f / (wnorm + 1e-8f)) : 1.0f;
        out[loss_off] = (__ldcg(&g_sv) + red2[0]) / numel;
    }
    __syncthreads();
    const float sc = sc_sh;
#pragma unroll
    for (int e = 0; e < 8; e++)
        out[nw_off + e * 512 + tid] = nwv[e] * sc;
    if (tid < 3) out[g_off + tid] = gates_sh[tid];

    // re-zero scratch for next graph replay
    __syncthreads();
    for (int i = tid; i < D * D; i += 512) { g_G1[i] = 0.0f; g_G2[i] = 0.0f; }
    if (tid < D) g_ksum[tid] = 0.0f;
    if (tid == 0) { g_sv = 0.0f; g_done = 0; }
}

extern "C" void kernel_launch(void* const* d_in, const int* in_sizes, int n_in,
                              void* d_out, int out_size) {
    const float* k  = (const float*)d_in[0];
    const float* v  = (const float*)d_in[1];
    const float* W  = (const float*)d_in[2];
    const float* gw = (const float*)d_in[3];
    const float* gb = (const float*)d_in[4];
    const float* S  = (const float*)d_in[5];
    float* out = (float*)d_out;

    const int N = in_sizes[0] / D;

    cudaFuncSetAttribute(titans_main_kernel,
                         cudaFuncAttributeMaxDynamicSharedMemorySize, SMEM_BYTES);

    titans_main_kernel<<<148, 512, SMEM_BYTES>>>(k, v, W, gw, gb, S, out, N);
}

// round 17
// speedup vs baseline: 1.3067x; 1.1402x over previous
#include <cuda_runtime.h>
#include <cuda_fp16.h>
#include <cstdint>

// TitansMemoryModule — R16: R12 main kernel verbatim + ONE combined epilogue kernel.
//   retrieved = k @ W^T ; G1 = k^T k (upper blocks, symmetric) ; G2 = v^T k
// 512 thr: w0-7 producers, w8-11 GEMM1 (M=32), w12-15 reductions.

#define D     64
#define TILE  128
#define PH    72
#define DEPTH 5

static constexpr int KBUF  = TILE * PH;
static constexpr int STAGE = 2 * KBUF;
static constexpr int SMEM_HALVES = DEPTH * STAGE + D * PH;
static constexpr int SMEM_BYTES  = SMEM_HALVES * 2;   // 193536 B (leaves ~35KB L1)

__device__ float g_G1[D * D];     // zero-init at load; re-zeroed by epilogue
__device__ float g_G2[D * D];
__device__ float g_ksum[D];
__device__ float g_sv;

__device__ __forceinline__ uint32_t sh_u32(const void* p) {
    return (uint32_t)__cvta_generic_to_shared(p);
}
__device__ __forceinline__ void ldsm4(uint32_t& r0, uint32_t& r1, uint32_t& r2, uint32_t& r3, uint32_t a) {
    asm volatile("ldmatrix.sync.aligned.m8n8.x4.shared.b16 {%0,%1,%2,%3},[%4];"
                 : "=r"(r0), "=r"(r1), "=r"(r2), "=r"(r3) : "r"(a));
}
__device__ __forceinline__ void ldsm4t(uint32_t& r0, uint32_t& r1, uint32_t& r2, uint32_t& r3, uint32_t a) {
    asm volatile("ldmatrix.sync.aligned.m8n8.x4.trans.shared.b16 {%0,%1,%2,%3},[%4];"
                 : "=r"(r0), "=r"(r1), "=r"(r2), "=r"(r3) : "r"(a));
}
__device__ __forceinline__ void mma16(float* c,
                                      uint32_t a0, uint32_t a1, uint32_t a2, uint32_t a3,
                                      uint32_t b0, uint32_t b1) {
    asm volatile("mma.sync.aligned.m16n8k16.row.col.f32.f16.f16.f32 "
                 "{%0,%1,%2,%3},{%4,%5,%6,%7},{%8,%9},{%0,%1,%2,%3};"
                 : "+f"(c[0]), "+f"(c[1]), "+f"(c[2]), "+f"(c[3])
                 : "r"(a0), "r"(a1), "r"(a2), "r"(a3), "r"(b0), "r"(b1));
}
__device__ __forceinline__ void mbar_init(uint32_t a, uint32_t cnt) {
    asm volatile("mbarrier.init.shared.b64 [%0], %1;" :: "r"(a), "r"(cnt) : "memory");
}
__device__ __forceinline__ void mbar_arrive(uint32_t a) {
    asm volatile("mbarrier.arrive.shared.b64 _, [%0];" :: "r"(a) : "memory");
}
__device__ __forceinline__ void mbar_wait(uint32_t a, uint32_t parity) {
    asm volatile(
        "{\n\t.reg .pred P;\n"
        "WL_%=:\n\t"
        "mbarrier.try_wait.parity.acquire.cta.shared::cta.b64 P, [%0], %1, 0x989680;\n\t"
        "@P bra WD_%=;\n\t"
        "bra WL_%=;\n"
        "WD_%=:\n\t}"
        :: "r"(a), "r"(parity) : "memory");
}

// ---- reduction fragment helpers ----
__device__ __forceinline__ void ldAfrag(uint32_t* f, const __half* mb, int sb, int ar, int lane) {
    const int asel = ((lane >> 4) << 3) + (lane & 7);
    const int aoff = ((lane >> 3) & 1) * 8;
    ldsm4t(f[0], f[1], f[2], f[3], sh_u32(&mb[(sb + asel) * PH + ar * 16 + aoff]));
}
__device__ __forceinline__ void ldBfrag(uint32_t* f, const __half* kb, int sb, int ac, int lane) {
    const int bsel = ((lane >> 3) & 1) * 8 + (lane & 7);
    const int boff = (lane >> 4) * 8;
    ldsm4t(f[0], f[1], f[2], f[3], sh_u32(&kb[(sb + bsel) * PH + ac * 16 + boff]));
}
__device__ __forceinline__ void bmma(float* acc, const uint32_t* A, const uint32_t* B) {
    mma16(acc,     A[0], A[1], A[2], A[3], B[0], B[1]);
    mma16(acc + 4, A[0], A[1], A[2], A[3], B[2], B[3]);
}

// writeout tables: enc = src<<4 | ar<<2 | ac
static __device__ const int RW_TBL[4][7] = {
    { 0,  1,  2,  3,  5,  6,  7},
    {10, 11, 15, 16, 17, 18, 19},
    {20, 21, 22, 23, 24, 25, 25},
    {26, 27, 28, 29, 30, 31, 31},
};
static __device__ const int RW_CNT[4] = {7, 7, 6, 6};

// Per-tile reduction routines; arrive-empty issued inside last kk after its loads.
__device__ __forceinline__ void red_tile_w0(float (&acc)[7][8], const __half* kb, const __half*,
                                            int lane, uint32_t ebar) {
#pragma unroll
    for (int kk = 0; kk < 8; kk++) {
        const int sb = kk * 16;
        uint32_t A0[4], A1[4], B[4][4];
        ldAfrag(A0, kb, sb, 0, lane); ldAfrag(A1, kb, sb, 1, lane);
#pragma unroll
        for (int ac = 0; ac < 4; ac++) ldBfrag(B[ac], kb, sb, ac, lane);
        if (kk == 7 && lane == 0) mbar_arrive(ebar);
        bmma(acc[0], A0, B[0]); bmma(acc[1], A0, B[1]);
        bmma(acc[2], A0, B[2]); bmma(acc[3], A0, B[3]);
        bmma(acc[4], A1, B[1]); bmma(acc[5], A1, B[2]); bmma(acc[6], A1, B[3]);
    }
}
__device__ __forceinline__ void red_tile_w1(float (&acc)[7][8], const __half* kb, const __half* vb,
                                            int lane, uint32_t ebar) {
#pragma unroll
    for (int kk = 0; kk < 8; kk++) {
        const int sb = kk * 16;
        uint32_t A2[4], A3[4], AV[4], B[4][4];
        ldAfrag(A2, kb, sb, 2, lane); ldAfrag(A3, kb, sb, 3, lane); ldAfrag(AV, vb, sb, 0, lane);
#pragma unroll
        for (int ac = 0; ac < 4; ac++) ldBfrag(B[ac], kb, sb, ac, lane);
        if (kk == 7 && lane == 0) mbar_arrive(ebar);
        bmma(acc[0], A2, B[2]); bmma(acc[1], A2, B[3]); bmma(acc[2], A3, B[3]);
        bmma(acc[3], AV, B[0]); bmma(acc[4], AV, B[1]);
        bmma(acc[5], AV, B[2]); bmma(acc[6], AV, B[3]);
    }
}
__device__ __forceinline__ void red_tile_w2(float (&acc)[7][8], const __half* kb, const __half* vb,
                                            int lane, uint32_t ebar) {
#pragma unroll
    for (int kk = 0; kk < 8; kk++) {
        const int sb = kk * 16;
        uint32_t A1[4], A2[4], B[4][4];
        ldAfrag(A1, vb, sb, 1, lane); ldAfrag(A2, vb, sb, 2, lane);
#pragma unroll
        for (int ac = 0; ac < 4; ac++) ldBfrag(B[ac], kb, sb, ac, lane);
        if (kk == 7 && lane == 0) mbar_arrive(ebar);
        bmma(acc[0], A1, B[0]); bmma(acc[1], A1, B[1]);
        bmma(acc[2], A1, B[2]); bmma(acc[3], A1, B[3]);
        bmma(acc[4], A2, B[0]); bmma(acc[5], A2, B[1]);
    }
}
__device__ __forceinline__ void red_tile_w3(float (&acc)[7][8], const __half* kb, const __half* vb,
                                            int lane, uint32_t ebar) {
#pragma unroll
    for (int kk = 0; kk < 8; kk++) {
        const int sb = kk * 16;
        uint32_t A2[4], A3[4], B[4][4];
        ldAfrag(A2, vb, sb, 2, lane); ldAfrag(A3, vb, sb, 3, lane);
#pragma unroll
        for (int ac = 0; ac < 4; ac++) ldBfrag(B[ac], kb, sb, ac, lane);
        if (kk == 7 && lane == 0) mbar_arrive(ebar);
        bmma(acc[0], A2, B[2]); bmma(acc[1], A2, B[3]);
        bmma(acc[2], A3, B[0]); bmma(acc[3], A3, B[1]);
        bmma(acc[4], A3, B[2]); bmma(acc[5], A3, B[3]);
    }
}

__global__ __launch_bounds__(512, 1)
void titans_main_kernel(const float* __restrict__ kmat,
                        const float* __restrict__ vmat,
                        const float* __restrict__ W,
                        float* __restrict__ ret,
                        int N) {
    extern __shared__ __half sh[];
    __shared__ uint64_t mbar[2 * DEPTH];
    __half* wsh = sh + DEPTH * STAGE;

    const int tid  = threadIdx.x;
    const int lane = tid & 31;
    const int warp = tid >> 5;

    if (tid == 0) {
#pragma unroll
        for (int s = 0; s < DEPTH; s++) {
            mbar_init(sh_u32(&mbar[s]), 8);            // full: 8 producer warps
            mbar_init(sh_u32(&mbar[DEPTH + s]), 8);    // empty: 8 consumer warps
        }
    }
    for (int i = tid; i < D * D; i += 512)
        wsh[(i >> 6) * PH + (i & 63)] = __float2half(W[i]);
    __syncthreads();

    const int grid   = gridDim.x;
    const int ntiles = N / TILE;

    if (warp < 8) {
        // ======== PRODUCERS: w0-3 k, w4-7 v (cross-tile register prefetch) ========
        const bool isK  = warp < 4;
        const int  pt   = isK ? tid : (tid - 128);
        const int  qcol = (pt & 15) * 4;
        const float4* src = reinterpret_cast<const float4*>(isK ? kmat : vmat);
        const int  boff = isK ? 0 : KBUF;

        float acc4[4] = {0.f, 0.f, 0.f, 0.f};

        float4 c0[8], c1r[8];
        {
            const float4* t0 = src + (size_t)blockIdx.x * 2048;
#pragma unroll
            for (int j = 0; j < 8; j++) c0[j]  = __ldcs(&t0[pt + j * 128]);
#pragma unroll
            for (int j = 0; j < 8; j++) c1r[j] = __ldcs(&t0[pt + (j + 8) * 128]);
        }

        int stage = 0, phase = 1;
        for (int tile = blockIdx.x; tile < ntiles; tile += grid) {
            int nt = tile + grid; if (nt >= ntiles) nt = tile;
            const float4* tn = src + (size_t)nt * 2048;

            mbar_wait(sh_u32(&mbar[DEPTH + stage]), phase);
            __half* dst = sh + stage * STAGE + boff;

#pragma unroll
            for (int j = 0; j < 8; j++) {
                float4 x = c0[j];
                int r = (pt + j * 128) >> 4;
                if (isK) { acc4[0] += x.x; acc4[1] += x.y; acc4[2] += x.z; acc4[3] += x.w; }
                else     { acc4[0] += x.x * x.x + x.y * x.y + x.z * x.z + x.w * x.w; }
                __half2 h01 = __floats2half2_rn(x.x, x.y);
                __half2 h23 = __floats2half2_rn(x.z, x.w);
                *reinterpret_cast<uint2*>(&dst[r * PH + qcol]) =
                    make_uint2(*reinterpret_cast<uint32_t*>(&h01), *reinterpret_cast<uint32_t*>(&h23));
            }
#pragma unroll
            for (int j = 0; j < 8; j++) c0[j] = __ldcs(&tn[pt + j * 128]);

#pragma unroll
            for (int j = 0; j < 8; j++) {
                float4 x = c1r[j];
                int r = (pt + (j + 8) * 128) >> 4;
                if (isK) { acc4[0] += x.x; acc4[1] += x.y; acc4[2] += x.z; acc4[3] += x.w; }
                else     { acc4[0] += x.x * x.x + x.y * x.y + x.z * x.z + x.w * x.w; }
                __half2 h01 = __floats2half2_rn(x.x, x.y);
                __half2 h23 = __floats2half2_rn(x.z, x.w);
                *reinterpret_cast<uint2*>(&dst[r * PH + qcol]) =
                    make_uint2(*reinterpret_cast<uint32_t*>(&h01), *reinterpret_cast<uint32_t*>(&h23));
            }
#pragma unroll
            for (int j = 0; j < 8; j++) c1r[j] = __ldcs(&tn[pt + (j + 8) * 128]);

            __syncwarp();
            if (lane == 0) mbar_arrive(sh_u32(&mbar[stage]));
            stage++; if (stage == DEPTH) { stage = 0; phase ^= 1; }
        }

        if (isK) {
#pragma unroll
            for (int c = 0; c < 4; c++) atomicAdd(&g_ksum[qcol + c], acc4[c]);
        } else {
            float sv = acc4[0];
#pragma unroll
            for (int off = 16; off > 0; off >>= 1) sv += __shfl_xor_sync(0xFFFFFFFF, sv, off);
            if (lane == 0) atomicAdd(&g_sv, sv);
        }

    } else if (warp < 12) {
        // ======== GEMM1 warps (4): each M=32 (two 16-row stripes), N=64 ========
        const int widx = warp - 8;
        const int lp = lane >> 2, lq = lane & 3;

        uint32_t wr[4][4][4];
#pragma unroll
        for (int kk = 0; kk < 4; kk++)
#pragma unroll
            for (int j = 0; j < 4; j++) {
                const int bt = (2 * j + (lane >> 4)) * 8 + (lane & 7);
                const int bc = kk * 16 + ((lane >> 3) & 1) * 8;
                ldsm4(wr[kk][j][0], wr[kk][j][1], wr[kk][j][2], wr[kk][j][3],
                      sh_u32(&wsh[bt * PH + bc]));
            }

        int stage = 0, phase = 0;
        for (int tile = blockIdx.x; tile < ntiles; tile += grid) {
            mbar_wait(sh_u32(&mbar[stage]), phase);
            const __half* kb = sh + stage * STAGE;

#pragma unroll
            for (int s2 = 0; s2 < 2; s2++) {
                const int rbase = widx * 32 + s2 * 16;
                uint32_t af[4][4];
#pragma unroll
                for (int kk = 0; kk < 4; kk++)
                    ldsm4(af[kk][0], af[kk][1], af[kk][2], af[kk][3],
                          sh_u32(&kb[(rbase + (lane & 15)) * PH + kk * 16 + ((lane >> 4) << 3)]));
                if (s2 == 1 && lane == 0) mbar_arrive(sh_u32(&mbar[DEPTH + stage]));

                float c1[8][4];
#pragma unroll
                for (int n = 0; n < 8; n++)
#pragma unroll
                    for (int i = 0; i < 4; i++) c1[n][i] = 0.0f;
#pragma unroll
                for (int kk = 0; kk < 4; kk++)
#pragma unroll
                    for (int j = 0; j < 4; j++) {
                        mma16(c1[2 * j],     af[kk][0], af[kk][1], af[kk][2], af[kk][3],
                              wr[kk][j][0], wr[kk][j][1]);
                        mma16(c1[2 * j + 1], af[kk][0], af[kk][1], af[kk][2], af[kk][3],
                              wr[kk][j][2], wr[kk][j][3]);
                    }

                const size_t gr0 = (size_t)(tile * TILE + rbase + lp) * D;
#pragma unroll
                for (int n = 0; n < 8; n++) {
                    const int col = n * 8 + 2 * lq;
                    __stcs(reinterpret_cast<float2*>(&ret[gr0 + col]),
                           make_float2(c1[n][0], c1[n][1]));
                    __stcs(reinterpret_cast<float2*>(&ret[gr0 + 8 * D + col]),
                           make_float2(c1[n][2], c1[n][3]));
                }
            }
            stage++; if (stage == DEPTH) { stage = 0; phase ^= 1; }
        }

    } else {
        // ======== Reduction warps (4): symmetric G1 + G2, early empty-arrive ========
        const int ridx = warp - 12;
        const int lp = lane >> 2, lq = lane & 3;

        float acc[7][8];
#pragma unroll
        for (int b = 0; b < 7; b++)
#pragma unroll
            for (int i = 0; i < 8; i++) acc[b][i] = 0.0f;

        int stage = 0, phase = 0;
        for (int tile = blockIdx.x; tile < ntiles; tile += grid) {
            mbar_wait(sh_u32(&mbar[stage]), phase);
            const __half* kb = sh + stage * STAGE;
            const __half* vb = kb + KBUF;
            const uint32_t ebar = sh_u32(&mbar[DEPTH + stage]);

            if      (ridx == 0) red_tile_w0(acc, kb, vb, lane, ebar);
            else if (ridx == 1) red_tile_w1(acc, kb, vb, lane, ebar);
            else if (ridx == 2) red_tile_w2(acc, kb, vb, lane, ebar);
            else                red_tile_w3(acc, kb, vb, lane, ebar);

            stage++; if (stage == DEPTH) { stage = 0; phase ^= 1; }
        }

        const int cnt = RW_CNT[ridx];
        for (int b = 0; b < cnt; b++) {
            const int enc = RW_TBL[ridx][b];
            const int src = (enc >> 4) & 1, ar = (enc >> 2) & 3, ac = enc & 3;
            float* gd = src ? g_G2 : g_G1;
            const int r0 = (ar * 16 + lp) * D + ac * 16;
            const int r1 = (ar * 16 + 8 + lp) * D + ac * 16;
            atomicAdd(&gd[r0 + 2 * lq],         acc[b][0]);
            atomicAdd(&gd[r0 + 2 * lq + 1],     acc[b][1]);
            atomicAdd(&gd[r1 + 2 * lq],         acc[b][2]);
            atomicAdd(&gd[r1 + 2 * lq + 1],     acc[b][3]);
            atomicAdd(&gd[r0 + 8 + 2 * lq],     acc[b][4]);
            atomicAdd(&gd[r0 + 8 + 2 * lq + 1], acc[b][5]);
            atomicAdd(&gd[r1 + 8 + 2 * lq],     acc[b][6]);
            atomicAdd(&gd[r1 + 8 + 2 * lq + 1], acc[b][7]);
        }
    }
}

// ================= combined epilogue: ONE kernel, 1 block x 512 threads =================
__global__ void titans_final(const float* __restrict__ W,
                             const float* __restrict__ gate_w,
                             const float* __restrict__ gate_b,
                             const float* __restrict__ S,
                             float* __restrict__ out,
                             int N) {
    __shared__ float Wf[D * D];
    __shared__ float G1m[D * D];
    __shared__ float G2f[D * D];
    __shared__ float red[512], red2[512];
    __shared__ float gates_sh[3];
    __shared__ float sc_sh;
    const int tid  = threadIdx.x;
    const int lane = tid & 31;
    const int warp = tid >> 5;
    const float numel = (float)N * (float)D;

    const size_t loss_off = (size_t)N * D;
    const size_t nw_off   = loss_off + 1;
    const size_t ns_off   = nw_off + D * D;
    const size_t g_off    = ns_off + D * D;

    if (warp < 3) {
        const float invN = 1.0f / (float)N;
        float s = gate_w[warp * D + lane]      * (g_ksum[lane]      * invN)
                + gate_w[warp * D + 32 + lane] * (g_ksum[32 + lane] * invN);
#pragma unroll
        for (int off = 16; off > 0; off >>= 1)
            s += __shfl_xor_sync(0xFFFFFFFF, s, off);
        if (lane == 0)
            gates_sh[warp] = 1.0f / (1.0f + __expf(-(s + gate_b[warp])));
    }
    for (int i = tid; i < D * D; i += 512) {
        Wf[i]  = W[i];
        G2f[i] = g_G2[i];
        const int j = i >> 6, d = i & 63;
        G1m[i] = ((j >> 4) <= (d >> 4)) ? g_G1[i] : g_G1[(d << 6) | j];
    }
    __syncthreads();

    const float alpha = gates_sh[0];
    const float eta   = gates_sh[1];
    const float theta = gates_sh[2];

    float nwv[8];
    float ssp = 0.0f, dlp = 0.0f;
#pragma unroll
    for (int e = 0; e < 8; e++) {
        const int idx = e * 512 + tid;
        const int j = idx >> 6, dp = idx & 63;
        float a = 0.0f;
#pragma unroll 8
        for (int d = 0; d < D; d++)
            a += Wf[j * D + d] * G1m[d * D + dp];
        const float w  = Wf[idx];
        const float g2 = G2f[idx];
        float g = (a - g2) * (2.0f / numel);
        g = fminf(1.0f, fmaxf(-1.0f, g));
        const float ns = eta * S[idx] - 0.01f * theta * g;
        const float nw = (1.0f - alpha) * w + ns;
        out[ns_off + idx] = ns;
        nwv[e] = nw;
        ssp += nw * nw;
        dlp += (a - 2.0f * g2) * w;
    }
    red[tid]  = ssp;
    red2[tid] = dlp;
    __syncthreads();
#pragma unroll
    for (int s = 256; s > 0; s >>= 1) {
        if (tid < s) { red[tid] += red[tid + s]; red2[tid] += red2[tid + s]; }
        __syncthreads();
    }
    if (tid == 0) {
        float wnorm = sqrtf(red[0]);
        sc_sh = (wnorm > 10.0f) ? (10.0f / (wnorm + 1e-8f)) : 1.0f;
        out[loss_off] = (g_sv + red2[0]) / numel;
    }
    __syncthreads();
    const float sc = sc_sh;
#pragma unroll
    for (int e = 0; e < 8; e++)
        out[nw_off + e * 512 + tid] = nwv[e] * sc;
    if (tid < 3) out[g_off + tid] = gates_sh[tid];

    // re-zero scratch for next graph replay
    __syncthreads();
    for (int i = tid; i < D * D; i += 512) { g_G1[i] = 0.0f; g_G2[i] = 0.0f; }
    if (tid < D) g_ksum[tid] = 0.0f;
    if (tid == 0) g_sv = 0.0f;
}

extern "C" void kernel_launch(void* const* d_in, const int* in_sizes, int n_in,
                              void* d_out, int out_size) {
    const float* k  = (const float*)d_in[0];
    const float* v  = (const float*)d_in[1];
    const float* W  = (const float*)d_in[2];
    const float* gw = (const float*)d_in[3];
    const float* gb = (const float*)d_in[4];
    const float* S  = (const float*)d_in[5];
    float* out = (float*)d_out;

    const int N = in_sizes[0] / D;

    cudaFuncSetAttribute(titans_main_kernel,
                         cudaFuncAttributeMaxDynamicSharedMemorySize, SMEM_BYTES);

    titans_main_kernel<<<148, 512, SMEM_BYTES>>>(k, v, W, out, N);
    titans_final<<<1, 512>>>(W, gw, gb, S, out, N);
}